// round 16
// baseline (speedup 1.0000x reference)
#include <cuda_runtime.h>
#include <cuda_fp16.h>
#include <cstdint>
#include <math.h>

// ---------------- problem constants ----------------
#define NB   16384
#define ZLD  513
#define XK   1024
#define HD   1024
#define LD   256
#define OUTC 513

// ---------------- scratch ----------------
__device__ __half g_X [NB * XK];     // activations fp16
__device__ __half g_H1[NB * HD];
__device__ __half g_H2[NB * HD];
__device__ float  g_inv[LD];         // 1 / safe_den(diffusion)
// transposed fp16 weights: Wt[n*K+k] = W[k*N+n]
__device__ __half g_Wh1[HD * 512];
__device__ __half g_Wc1[HD * XK];
__device__ __half g_Wh2[LD * HD];
__device__ __half g_Wc2[LD * HD];

// ---------------- helpers ----------------
__device__ __forceinline__ uint32_t smem_u32(const void* p) {
    uint32_t a;
    asm("{ .reg .u64 t; cvta.to.shared.u64 t, %1; cvt.u32.u64 %0, t; }" : "=r"(a) : "l"(p));
    return a;
}
__device__ __forceinline__ void ldsm4(uint32_t (&r)[4], uint32_t addr) {
    asm volatile("ldmatrix.sync.aligned.m8n8.x4.shared.b16 {%0,%1,%2,%3}, [%4];"
        : "=r"(r[0]), "=r"(r[1]), "=r"(r[2]), "=r"(r[3]) : "r"(addr));
}
__device__ __forceinline__ void mma16816(float (&d)[4], const uint32_t (&a)[4],
                                         uint32_t b0, uint32_t b1) {
    asm volatile("mma.sync.aligned.m16n8k16.row.col.f32.f16.f16.f32 "
        "{%0,%1,%2,%3}, {%4,%5,%6,%7}, {%8,%9}, {%0,%1,%2,%3};"
        : "+f"(d[0]), "+f"(d[1]), "+f"(d[2]), "+f"(d[3])
        : "r"(a[0]), "r"(a[1]), "r"(a[2]), "r"(a[3]), "r"(b0), "r"(b1));
}
__device__ __forceinline__ void cpasync16(uint32_t saddr, const void* g) {
    asm volatile("cp.async.cg.shared.global [%0], [%1], 16;" :: "r"(saddr), "l"(g));
}
__device__ __forceinline__ void cp_commit() { asm volatile("cp.async.commit_group;"); }
__device__ __forceinline__ void cp_wait1()  { asm volatile("cp.async.wait_group 1;"  ::: "memory"); }
__device__ __forceinline__ void cp_wait0()  { asm volatile("cp.async.wait_group 0;"  ::: "memory"); }
__device__ __forceinline__ void gdc_wait()  { asm volatile("griddepcontrol.wait;" ::: "memory"); }

// ---------------------------------------------------------------------------
// K0 (merged, vectorized):
//  range A: X build | range B: diffusion_out fill | range C: drift head +
//           dkl-slot zero + inv_sden | range D: weight transposes
// ---------------------------------------------------------------------------
#define BLK_X   (NB * XK / 1024)
#define BLK_D   (NB * OUTC / 1024)
#define BLK_R   (NB / 4)
#define BLK_W   2048

__global__ void prep_kernel(const float* __restrict__ z,
                            const float* __restrict__ ctx,
                            const float* __restrict__ ts,
                            const float* __restrict__ tp,
                            const float* __restrict__ inv_mass,
                            const float* __restrict__ diffusion,
                            const float* __restrict__ Wh1,
                            const float* __restrict__ Wc1,
                            const float* __restrict__ Wh2,
                            const float* __restrict__ Wc2,
                            float* __restrict__ out)
{
    __shared__ float s[32][33];
    int b = blockIdx.x;
    int tid = threadIdx.x;

    if (b < BLK_X) {
        int idx4 = (b * 256 + tid) * 4;
        float t = tp[0];
        int i = 0;
        #pragma unroll
        for (int j = 0; j < 16; ++j) i += (ts[j] <= t) ? 1 : 0;
        if (i > 15) i = 15;
        int row = idx4 >> 10, c0 = idx4 & 1023;
        float v0, v1, v2, v3;
        if (c0 >= 512) {
            const float4 cv = *reinterpret_cast<const float4*>(
                ctx + ((long)row * 16 + i) * 512 + (c0 - 512));
            v0 = cv.x; v1 = cv.y; v2 = cv.z; v3 = cv.w;
        } else {
            const float* zr = z + (long)row * ZLD + c0;
            v0 = zr[0]; v1 = zr[1]; v2 = zr[2]; v3 = zr[3];
        }
        __half2 h0; h0.x = __float2half_rn(v0); h0.y = __float2half_rn(v1);
        __half2 h1; h1.x = __float2half_rn(v2); h1.y = __float2half_rn(v3);
        uint2 pk;
        pk.x = *reinterpret_cast<uint32_t*>(&h0);
        pk.y = *reinterpret_cast<uint32_t*>(&h1);
        *reinterpret_cast<uint2*>(&g_X[idx4]) = pk;
    } else if (b < BLK_X + BLK_D) {
        long f4 = (long)(b - BLK_X) * 1024 + tid * 4;
        int row = (int)(f4 / OUTC);
        int c   = (int)(f4 - (long)row * OUTC);
        float4 v;
        float* vp = &v.x;
        #pragma unroll
        for (int k = 0; k < 4; ++k) {
            int cc = c + k;
            if (cc >= OUTC) cc -= OUTC;
            vp[k] = (cc >= 256 && cc < 512) ? diffusion[cc - 256] : 0.f;
        }
        *reinterpret_cast<float4*>(out + (long)NB * OUTC + f4) = v;
    } else if (b < BLK_X + BLK_D + BLK_R) {
        int rb = b - (BLK_X + BLK_D);
        int row = rb * 4 + (tid >> 6);
        int l   = tid & 63;
        int j0  = l * 4;
        const float* zr = z + (long)row * ZLD + 256 + j0;
        float* orow = out + (long)row * OUTC + j0;
        #pragma unroll
        for (int k = 0; k < 4; ++k)
            orow[k] = inv_mass[j0 + k] * zr[k];
        if (l == 0) out[(long)row * OUTC + 512] = 0.f;   // dkl accumulator init
        if (rb == 0) {                                   // inv_sden (once)
            float dif = diffusion[tid];
            float sgn  = (dif > 0.f) ? 1.f : ((dif < 0.f) ? -1.f : 0.f);
            float sden = (fabsf(dif) > 1e-7f) ? dif : sgn * 1e-7f;
            g_inv[tid] = 1.f / sden;
        }
    } else {
        int wb = b - (BLK_X + BLK_D + BLK_R);
        const float* W; int K, N; __half* T; int base;
        if (wb < 512)       { W = Wh1; K = 512;  N = HD; T = g_Wh1; base = 0;    }
        else if (wb < 1536) { W = Wc1; K = 1024; N = HD; T = g_Wc1; base = 512;  }
        else if (wb < 1792) { W = Wh2; K = 1024; N = LD; T = g_Wh2; base = 1536; }
        else                { W = Wc2; K = 1024; N = LD; T = g_Wc2; base = 1792; }
        int idx = wb - base;
        int nb  = N / 32;
        int n0  = (idx % nb) * 32;
        int k0  = (idx / nb) * 32;
        int x = tid & 31, y0 = tid >> 5;
        #pragma unroll
        for (int r = 0; r < 4; ++r) {
            int y = y0 + r * 8;
            s[y][x] = W[(long)(k0 + y) * N + n0 + x];
        }
        __syncthreads();
        #pragma unroll
        for (int r = 0; r < 4; ++r) {
            int y = y0 + r * 8;
            T[(long)(n0 + y) * K + k0 + x] = __float2half_rn(s[x][y]);
        }
    }
}

// ---------------------------------------------------------------------------
// Layer-1 GEMM (unchanged best config): C = tanh(A @ W^T + bias), batched z.
// ---------------------------------------------------------------------------
#define BK      32
#define A_OFF   0u
#define B_OFF   8192u
#define STAGE   16384
#define NSTAGE  3

__global__ __launch_bounds__(256, 2)
void mma_gemm_l1(const __half* __restrict__ A0, const __half* __restrict__ B0,
                 const float* __restrict__ bias0, __half* C0, int K0,
                 const __half* __restrict__ A1, const __half* __restrict__ B1,
                 const float* __restrict__ bias1, __half* C1, int K1,
                 int lda, int ldc)
{
    extern __shared__ char smem[];
    const uint32_t sb = smem_u32(smem);
    const int tid  = threadIdx.x;
    const int wid  = tid >> 5;
    const int lane = tid & 31;
    const int wm   = wid >> 2;
    const int wn   = wid & 3;
    const int m0   = blockIdx.y * 128;
    const int n0   = blockIdx.x * 128;

    const int zz = blockIdx.z;
    const __half*  A   = zz ? A1   : A0;
    const __half*  B   = zz ? B1   : B0;
    const float*  bias = zz ? bias1 : bias0;
    __half*        C   = zz ? C1   : C0;
    const int      K   = zz ? K1   : K0;

    const int crow  = tid >> 1;
    const int chalf = tid & 1;
    const uint32_t csw = (uint32_t)((crow & 6) << 3);
    const uint32_t cd0 = (uint32_t)(crow * 64) + (((uint32_t)(chalf * 32) + 0u)  ^ csw);
    const uint32_t cd1 = (uint32_t)(crow * 64) + (((uint32_t)(chalf * 32) + 16u) ^ csw);

    const __half* gA = A + (size_t)(m0 + crow) * lda + chalf * 16;
    const __half* gB = B + (size_t)(n0 + crow) * K   + chalf * 16;

    const int g  = lane >> 3;
    const int l8 = lane & 7;
    const uint32_t fsw = (uint32_t)((l8 & 6) << 3);
    const uint32_t a_row = (uint32_t)(wm * 64 + (g & 1) * 8 + l8);
    const uint32_t b_row = (uint32_t)(wn * 32 + (g >> 1) * 8 + l8);
    uint32_t aCk[2], bCk[2];
    #pragma unroll
    for (int ka = 0; ka < 2; ++ka) {
        aCk[ka] = ((uint32_t)((g >> 1) * 16 + ka * 32)) ^ fsw;
        bCk[ka] = ((uint32_t)((g & 1)  * 16 + ka * 32)) ^ fsw;
    }
    const uint32_t aBase = a_row * 64u;
    const uint32_t bBase = b_row * 64u;

    float acc[4][4][4];
    #pragma unroll
    for (int i = 0; i < 4; ++i)
        #pragma unroll
        for (int j = 0; j < 4; ++j)
            #pragma unroll
            for (int r = 0; r < 4; ++r) acc[i][j][r] = 0.f;

    const int NC = K / BK;

    gdc_wait();

    #pragma unroll
    for (int p = 0; p < 2; ++p) {
        uint32_t st = sb + (uint32_t)p * STAGE;
        const int kc = p * BK;
        cpasync16(st + A_OFF + cd0, gA + kc);
        cpasync16(st + A_OFF + cd1, gA + kc + 8);
        cpasync16(st + B_OFF + cd0, gB + kc);
        cpasync16(st + B_OFF + cd1, gB + kc + 8);
        cp_commit();
    }

    int s_cons = 0, s_load = 2;
    for (int c = 0; c < NC; ++c) {
        cp_wait1();
        __syncthreads();

        if (c + 2 < NC) {
            const int kc = (c + 2) * BK;
            uint32_t st = sb + (uint32_t)s_load * STAGE;
            cpasync16(st + A_OFF + cd0, gA + kc);
            cpasync16(st + A_OFF + cd1, gA + kc + 8);
            cpasync16(st + B_OFF + cd0, gB + kc);
            cpasync16(st + B_OFF + cd1, gB + kc + 8);
        }
        cp_commit();

        const uint32_t st = sb + (uint32_t)s_cons * STAGE;
        uint32_t bf[2][2][4];
        #pragma unroll
        for (int ka = 0; ka < 2; ++ka) {
            ldsm4(bf[ka][0], st + B_OFF + bBase +    0u + bCk[ka]);
            ldsm4(bf[ka][1], st + B_OFF + bBase + 1024u + bCk[ka]);
        }
        #pragma unroll
        for (int i = 0; i < 4; ++i) {
            uint32_t af[2][4];
            ldsm4(af[0], st + A_OFF + aBase + (uint32_t)(i * 1024) + aCk[0]);
            ldsm4(af[1], st + A_OFF + aBase + (uint32_t)(i * 1024) + aCk[1]);
            #pragma unroll
            for (int ka = 0; ka < 2; ++ka) {
                #pragma unroll
                for (int j = 0; j < 4; ++j) {
                    mma16816(acc[i][j], af[ka],
                             bf[ka][j >> 1][(j & 1) * 2], bf[ka][j >> 1][(j & 1) * 2 + 1]);
                }
            }
        }
        if (++s_cons == NSTAGE) s_cons = 0;
        if (++s_load == NSTAGE) s_load = 0;
    }

    const int quad = lane >> 2;
    const int tq   = lane & 3;
    #pragma unroll
    for (int i = 0; i < 4; ++i) {
        #pragma unroll
        for (int j = 0; j < 4; ++j) {
            const int m = m0 + wm * 64 + i * 16 + quad;
            const int cc = n0 + wn * 32 + j * 8 + tq * 2;
            const float bb0 = __ldg(bias + cc);
            const float bb1 = __ldg(bias + cc + 1);
            float v00 = tanhf(acc[i][j][0] + bb0);
            float v01 = tanhf(acc[i][j][1] + bb1);
            float v10 = tanhf(acc[i][j][2] + bb0);
            float v11 = tanhf(acc[i][j][3] + bb1);
            __half2 p0; p0.x = __float2half_rn(v00); p0.y = __float2half_rn(v01);
            __half2 p1; p1.x = __float2half_rn(v10); p1.y = __float2half_rn(v11);
            *reinterpret_cast<__half2*>(C + (size_t)m * ldc + cc)       = p0;
            *reinterpret_cast<__half2*>(C + (size_t)(m + 8) * ldc + cc) = p1;
        }
    }
}

// ---------------------------------------------------------------------------
// Fused layer-2: per CTA compute P1 (H1@Wh2+bh2) AND P2 (H2@Wc2+bc2) for the
// same 128x128 tile (dual accumulators). Epilogue:
//   - dkl partials ((p1-p2)*inv)^2 -> tq-shfl reduce -> atomicAdd out[.,512]
//   - P2 staged in smem -> coalesced direct write to out[.,256..384)
// Stage = A1 8K | A2 8K | B1 8K | B2 8K = 32KB, 3 stages = 96KB, 1 CTA/SM.
// ---------------------------------------------------------------------------
#define F_A1  0u
#define F_A2  8192u
#define F_B1  16384u
#define F_B2  24576u
#define F_STAGE 32768
#define F_K   1024

__global__ __launch_bounds__(256, 1)
void l2_fused(const __half* __restrict__ H1, const __half* __restrict__ H2,
              const __half* __restrict__ B1w, const __half* __restrict__ B2w,
              const float* __restrict__ bh2, const float* __restrict__ bc2,
              float* __restrict__ out)
{
    extern __shared__ char smem[];
    const uint32_t sb = smem_u32(smem);
    const int tid  = threadIdx.x;
    const int wid  = tid >> 5;
    const int lane = tid & 31;
    const int wm   = wid >> 2;
    const int wn   = wid & 3;
    const int m0   = blockIdx.y * 128;
    const int n0   = blockIdx.x * 128;     // 0 or 128 within L=256

    const int crow  = tid >> 1;
    const int chalf = tid & 1;
    const uint32_t csw = (uint32_t)((crow & 6) << 3);
    const uint32_t cd0 = (uint32_t)(crow * 64) + (((uint32_t)(chalf * 32) + 0u)  ^ csw);
    const uint32_t cd1 = (uint32_t)(crow * 64) + (((uint32_t)(chalf * 32) + 16u) ^ csw);

    const __half* gA1 = H1  + (size_t)(m0 + crow) * HD  + chalf * 16;
    const __half* gA2 = H2  + (size_t)(m0 + crow) * HD  + chalf * 16;
    const __half* gB1 = B1w + (size_t)(n0 + crow) * F_K + chalf * 16;
    const __half* gB2 = B2w + (size_t)(n0 + crow) * F_K + chalf * 16;

    const int g  = lane >> 3;
    const int l8 = lane & 7;
    const uint32_t fsw = (uint32_t)((l8 & 6) << 3);
    const uint32_t a_row = (uint32_t)(wm * 64 + (g & 1) * 8 + l8);
    const uint32_t b_row = (uint32_t)(wn * 32 + (g >> 1) * 8 + l8);
    uint32_t aCk[2], bCk[2];
    #pragma unroll
    for (int ka = 0; ka < 2; ++ka) {
        aCk[ka] = ((uint32_t)((g >> 1) * 16 + ka * 32)) ^ fsw;
        bCk[ka] = ((uint32_t)((g & 1)  * 16 + ka * 32)) ^ fsw;
    }
    const uint32_t aBase = a_row * 64u;
    const uint32_t bBase = b_row * 64u;

    float acc1[4][4][4], acc2[4][4][4];
    #pragma unroll
    for (int i = 0; i < 4; ++i)
        #pragma unroll
        for (int j = 0; j < 4; ++j)
            #pragma unroll
            for (int r = 0; r < 4; ++r) { acc1[i][j][r] = 0.f; acc2[i][j][r] = 0.f; }

    const int NC = F_K / BK;   // 32

    gdc_wait();

    #pragma unroll
    for (int p = 0; p < 2; ++p) {
        uint32_t st = sb + (uint32_t)p * F_STAGE;
        const int kc = p * BK;
        cpasync16(st + F_A1 + cd0, gA1 + kc);
        cpasync16(st + F_A1 + cd1, gA1 + kc + 8);
        cpasync16(st + F_A2 + cd0, gA2 + kc);
        cpasync16(st + F_A2 + cd1, gA2 + kc + 8);
        cpasync16(st + F_B1 + cd0, gB1 + kc);
        cpasync16(st + F_B1 + cd1, gB1 + kc + 8);
        cpasync16(st + F_B2 + cd0, gB2 + kc);
        cpasync16(st + F_B2 + cd1, gB2 + kc + 8);
        cp_commit();
    }

    int s_cons = 0, s_load = 2;
    for (int c = 0; c < NC; ++c) {
        cp_wait1();
        __syncthreads();

        if (c + 2 < NC) {
            const int kc = (c + 2) * BK;
            uint32_t st = sb + (uint32_t)s_load * F_STAGE;
            cpasync16(st + F_A1 + cd0, gA1 + kc);
            cpasync16(st + F_A1 + cd1, gA1 + kc + 8);
            cpasync16(st + F_A2 + cd0, gA2 + kc);
            cpasync16(st + F_A2 + cd1, gA2 + kc + 8);
            cpasync16(st + F_B1 + cd0, gB1 + kc);
            cpasync16(st + F_B1 + cd1, gB1 + kc + 8);
            cpasync16(st + F_B2 + cd0, gB2 + kc);
            cpasync16(st + F_B2 + cd1, gB2 + kc + 8);
        }
        cp_commit();

        const uint32_t st = sb + (uint32_t)s_cons * F_STAGE;
        #pragma unroll
        for (int ka = 0; ka < 2; ++ka) {
            uint32_t b1f[2][4], b2f[2][4];
            ldsm4(b1f[0], st + F_B1 + bBase +    0u + bCk[ka]);
            ldsm4(b1f[1], st + F_B1 + bBase + 1024u + bCk[ka]);
            ldsm4(b2f[0], st + F_B2 + bBase +    0u + bCk[ka]);
            ldsm4(b2f[1], st + F_B2 + bBase + 1024u + bCk[ka]);
            #pragma unroll
            for (int i = 0; i < 4; ++i) {
                uint32_t a1f[4], a2f[4];
                ldsm4(a1f, st + F_A1 + aBase + (uint32_t)(i * 1024) + aCk[ka]);
                ldsm4(a2f, st + F_A2 + aBase + (uint32_t)(i * 1024) + aCk[ka]);
                #pragma unroll
                for (int j = 0; j < 4; ++j) {
                    mma16816(acc1[i][j], a1f,
                             b1f[j >> 1][(j & 1) * 2], b1f[j >> 1][(j & 1) * 2 + 1]);
                    mma16816(acc2[i][j], a2f,
                             b2f[j >> 1][(j & 1) * 2], b2f[j >> 1][(j & 1) * 2 + 1]);
                }
            }
        }
        if (++s_cons == NSTAGE) s_cons = 0;
        if (++s_load == NSTAGE) s_load = 0;
    }

    // drain async copies, then reuse pipeline smem as the P2 staging tile
    cp_wait0();
    __syncthreads();
    float* sp2 = reinterpret_cast<float*>(smem);    // 128 x 128 fp32 = 64 KB

    const int quad = lane >> 2;
    const int tq   = lane & 3;
    #pragma unroll
    for (int i = 0; i < 4; ++i) {
        float rs0 = 0.f, rs1 = 0.f;
        const int ml0 = wm * 64 + i * 16 + quad;    // local rows
        const int ml1 = ml0 + 8;
        #pragma unroll
        for (int j = 0; j < 4; ++j) {
            const int cl = wn * 32 + j * 8 + tq * 2;   // local col in [0,128)
            const int gc = n0 + cl;                    // global col in [0,256)
            const float bh0 = __ldg(bh2 + gc);
            const float bh1 = __ldg(bh2 + gc + 1);
            const float bc0 = __ldg(bc2 + gc);
            const float bc1 = __ldg(bc2 + gc + 1);
            const float iv0 = g_inv[gc];
            const float iv1 = g_inv[gc + 1];

            float p1a = acc1[i][j][0] + bh0, p2a = acc2[i][j][0] + bc0;
            float p1b = acc1[i][j][1] + bh1, p2b = acc2[i][j][1] + bc1;
            float p1c = acc1[i][j][2] + bh0, p2c = acc2[i][j][2] + bc0;
            float p1d = acc1[i][j][3] + bh1, p2d = acc2[i][j][3] + bc1;

            sp2[ml0 * 128 + cl]     = p2a;
            sp2[ml0 * 128 + cl + 1] = p2b;
            sp2[ml1 * 128 + cl]     = p2c;
            sp2[ml1 * 128 + cl + 1] = p2d;

            float d0 = (p1a - p2a) * iv0, d1 = (p1b - p2b) * iv1;
            float d2 = (p1c - p2c) * iv0, d3 = (p1d - p2d) * iv1;
            rs0 += d0 * d0 + d1 * d1;
            rs1 += d2 * d2 + d3 * d3;
        }
        // reduce over tq lanes (bits 0..1 of lane)
        rs0 += __shfl_xor_sync(0xffffffffu, rs0, 1);
        rs0 += __shfl_xor_sync(0xffffffffu, rs0, 2);
        rs1 += __shfl_xor_sync(0xffffffffu, rs1, 1);
        rs1 += __shfl_xor_sync(0xffffffffu, rs1, 2);
        if (tq == 0) {
            atomicAdd(out + (size_t)(m0 + ml0) * OUTC + 512, rs0);
            atomicAdd(out + (size_t)(m0 + ml1) * OUTC + 512, rs1);
        }
    }
    __syncthreads();

    // coalesced P2 write: 64 passes, consecutive threads -> consecutive cols
    #pragma unroll 4
    for (int p = 0; p < 64; ++p) {
        int idx = p * 256 + tid;
        int r = idx >> 7, cl = idx & 127;
        out[(size_t)(m0 + r) * OUTC + 256 + n0 + cl] = sp2[r * 128 + cl];
    }
}

// ---------------------------------------------------------------------------
extern "C" void kernel_launch(void* const* d_in, const int* in_sizes, int n_in,
                              void* d_out, int out_size)
{
    const float* z    = (const float*)d_in[0];
    const float* ts   = (const float*)d_in[1];
    const float* t    = (const float*)d_in[2];
    const float* ctx  = (const float*)d_in[3];
    const float* im   = (const float*)d_in[4];
    const float* dif  = (const float*)d_in[5];
    const float* Wc1  = (const float*)d_in[6];
    const float* bc1  = (const float*)d_in[7];
    const float* Wc2  = (const float*)d_in[8];
    const float* bc2  = (const float*)d_in[9];
    const float* Wh1  = (const float*)d_in[10];
    const float* bh1  = (const float*)d_in[11];
    const float* Wh2  = (const float*)d_in[12];
    const float* bh2  = (const float*)d_in[13];
    float* out = (float*)d_out;

    __half *pX, *pH1, *pH2;
    __half *pWh1, *pWc1, *pWh2, *pWc2;
    cudaGetSymbolAddress((void**)&pX,  g_X);
    cudaGetSymbolAddress((void**)&pH1, g_H1);
    cudaGetSymbolAddress((void**)&pH2, g_H2);
    cudaGetSymbolAddress((void**)&pWh1, g_Wh1);
    cudaGetSymbolAddress((void**)&pWc1, g_Wc1);
    cudaGetSymbolAddress((void**)&pWh2, g_Wh2);
    cudaGetSymbolAddress((void**)&pWc2, g_Wc2);

    const int smem_l1 = NSTAGE * STAGE;     // 48 KB
    const int smem_l2 = NSTAGE * F_STAGE;   // 96 KB
    cudaFuncSetAttribute(mma_gemm_l1, cudaFuncAttributeMaxDynamicSharedMemorySize, smem_l1);
    cudaFuncSetAttribute(l2_fused,    cudaFuncAttributeMaxDynamicSharedMemorySize, smem_l2);

    // merged: X build + diffusion_out fill + drift head + inv_sden + wtrans
    prep_kernel<<<BLK_X + BLK_D + BLK_R + BLK_W, 256>>>(
        z, ctx, ts, t, im, dif, Wh1, Wc1, Wh2, Wc2, out);

    cudaLaunchAttribute pdl[1];
    pdl[0].id = cudaLaunchAttributeProgrammaticStreamSerialization;
    pdl[0].val.programmaticStreamSerializationAllowed = 1;

    // Layer 1 (batched): z=0 H1 = tanh(pm@Wh1+bh1) K=512 ; z=1 H2 = tanh(X@Wc1+bc1) K=1024
    {
        cudaLaunchConfig_t cfg = {};
        cfg.gridDim  = dim3(HD / 128, NB / 128, 2);
        cfg.blockDim = dim3(256, 1, 1);
        cfg.dynamicSmemBytes = smem_l1;
        cfg.stream = 0;
        cfg.attrs = pdl;
        cfg.numAttrs = 1;
        cudaLaunchKernelEx(&cfg, mma_gemm_l1,
            (const __half*)pX, (const __half*)pWh1, bh1, pH1, 512,
            (const __half*)pX, (const __half*)pWc1, bc1, pH2, 1024,
            XK, HD);
    }

    // Fused layer 2: P1/P2 dual-accumulator + dkl + direct P2 write
    {
        cudaLaunchConfig_t cfg = {};
        cfg.gridDim  = dim3(LD / 128, NB / 128, 1);
        cfg.blockDim = dim3(256, 1, 1);
        cfg.dynamicSmemBytes = smem_l2;
        cfg.stream = 0;
        cfg.attrs = pdl;
        cfg.numAttrs = 1;
        cudaLaunchKernelEx(&cfg, l2_fused,
            (const __half*)pH1, (const __half*)pH2,
            (const __half*)pWh2, (const __half*)pWc2,
            bh2, bc2, out);
    }
}

// round 17
// speedup vs baseline: 1.0205x; 1.0205x over previous
#include <cuda_runtime.h>
#include <cuda_fp16.h>
#include <cstdint>
#include <math.h>

// ---------------- problem constants ----------------
#define NB   16384
#define ZLD  513
#define XK   1024
#define HD   1024
#define LD   256
#define OUTC 513

// ---------------- scratch ----------------
__device__ __half g_X [NB * XK];     // activations fp16
__device__ __half g_H1[NB * HD];
__device__ __half g_H2[NB * HD];
__device__ float  g_P1[NB * LD];
__device__ float  g_P2[NB * LD];
// transposed fp16 weights: Wt[n*K+k] = W[k*N+n]
__device__ __half g_Wh1[HD * 512];
__device__ __half g_Wc1[HD * XK];
__device__ __half g_Wh2[LD * HD];
__device__ __half g_Wc2[LD * HD];

// ---------------- helpers ----------------
__device__ __forceinline__ uint32_t smem_u32(const void* p) {
    uint32_t a;
    asm("{ .reg .u64 t; cvta.to.shared.u64 t, %1; cvt.u32.u64 %0, t; }" : "=r"(a) : "l"(p));
    return a;
}
__device__ __forceinline__ void ldsm4(uint32_t (&r)[4], uint32_t addr) {
    asm volatile("ldmatrix.sync.aligned.m8n8.x4.shared.b16 {%0,%1,%2,%3}, [%4];"
        : "=r"(r[0]), "=r"(r[1]), "=r"(r[2]), "=r"(r[3]) : "r"(addr));
}
__device__ __forceinline__ void mma16816(float (&d)[4], const uint32_t (&a)[4],
                                         uint32_t b0, uint32_t b1) {
    asm volatile("mma.sync.aligned.m16n8k16.row.col.f32.f16.f16.f32 "
        "{%0,%1,%2,%3}, {%4,%5,%6,%7}, {%8,%9}, {%0,%1,%2,%3};"
        : "+f"(d[0]), "+f"(d[1]), "+f"(d[2]), "+f"(d[3])
        : "r"(a[0]), "r"(a[1]), "r"(a[2]), "r"(a[3]), "r"(b0), "r"(b1));
}
__device__ __forceinline__ void cpasync16(uint32_t saddr, const void* g) {
    asm volatile("cp.async.cg.shared.global [%0], [%1], 16;" :: "r"(saddr), "l"(g));
}
__device__ __forceinline__ void cp_commit() { asm volatile("cp.async.commit_group;"); }
__device__ __forceinline__ void cp_wait1()  { asm volatile("cp.async.wait_group 1;"  ::: "memory"); }
__device__ __forceinline__ void gdc_wait()  { asm volatile("griddepcontrol.wait;" ::: "memory"); }

// ---------------------------------------------------------------------------
// K0 (merged, vectorized):
//  range A: X build (searchsorted hoisted to 1 thread/block)
//  range B: diffusion_out flat float4 fill (uint32 index math)
//  range C: drift head | range D: weight transposes
// ---------------------------------------------------------------------------
#define BLK_X   (NB * XK / 1024)        // 16384
#define BLK_D   (NB * OUTC / 1024)      // 8208
#define BLK_R   (NB / 4)                // 4096
#define BLK_W   2048

__global__ void prep_kernel(const float* __restrict__ z,
                            const float* __restrict__ ctx,
                            const float* __restrict__ ts,
                            const float* __restrict__ tp,
                            const float* __restrict__ inv_mass,
                            const float* __restrict__ diffusion,
                            const float* __restrict__ Wh1,
                            const float* __restrict__ Wc1,
                            const float* __restrict__ Wh2,
                            const float* __restrict__ Wc2,
                            float* __restrict__ out)
{
    __shared__ float s[32][33];
    __shared__ int sh_i;
    int b = blockIdx.x;
    int tid = threadIdx.x;

    if (b < BLK_X) {
        // ---- X build: 4 consecutive cols per thread; ctx index once per block ----
        if (tid == 0) {
            float t = tp[0];
            int i = 0;
            #pragma unroll
            for (int j = 0; j < 16; ++j) i += (ts[j] <= t) ? 1 : 0;
            if (i > 15) i = 15;
            sh_i = i;
        }
        __syncthreads();
        int i = sh_i;
        uint32_t idx4 = (uint32_t)(b * 256 + tid) * 4u;
        uint32_t row = idx4 >> 10, c0 = idx4 & 1023u;
        float v0, v1, v2, v3;
        if (c0 >= 512u) {
            const float4 cv = *reinterpret_cast<const float4*>(
                ctx + ((long)row * 16 + i) * 512 + (c0 - 512u));
            v0 = cv.x; v1 = cv.y; v2 = cv.z; v3 = cv.w;
        } else {
            const float* zr = z + (long)row * ZLD + c0;
            v0 = zr[0]; v1 = zr[1]; v2 = zr[2]; v3 = zr[3];
        }
        __half2 h0; h0.x = __float2half_rn(v0); h0.y = __float2half_rn(v1);
        __half2 h1; h1.x = __float2half_rn(v2); h1.y = __float2half_rn(v3);
        uint2 pk;
        pk.x = *reinterpret_cast<uint32_t*>(&h0);
        pk.y = *reinterpret_cast<uint32_t*>(&h1);
        *reinterpret_cast<uint2*>(&g_X[idx4]) = pk;
    } else if (b < BLK_X + BLK_D) {
        // ---- diffusion_out flat fill (uint32 math; const-div -> mulhi) ----
        uint32_t f4 = (uint32_t)(b - BLK_X) * 1024u + (uint32_t)tid * 4u;
        uint32_t row = f4 / (uint32_t)OUTC;
        uint32_t c   = f4 - row * (uint32_t)OUTC;
        float4 v;
        float* vp = &v.x;
        #pragma unroll
        for (int k = 0; k < 4; ++k) {
            uint32_t cc = c + (uint32_t)k;
            if (cc >= (uint32_t)OUTC) cc -= (uint32_t)OUTC;
            vp[k] = (cc >= 256u && cc < 512u) ? diffusion[cc - 256u] : 0.f;
        }
        *reinterpret_cast<float4*>(out + (long)NB * OUTC + f4) = v;
    } else if (b < BLK_X + BLK_D + BLK_R) {
        // ---- drift head: 4 rows/block, 64 thr/row, 4 cols/thread ----
        int rb = b - (BLK_X + BLK_D);
        int row = rb * 4 + (tid >> 6);
        int j0  = (tid & 63) * 4;
        const float* zr = z + (long)row * ZLD + 256 + j0;
        float* orow = out + (long)row * OUTC + j0;
        #pragma unroll
        for (int k = 0; k < 4; ++k)
            orow[k] = inv_mass[j0 + k] * zr[k];
    } else {
        // ---- weight transposes: 32x32 tile per block, 256 threads ----
        int wb = b - (BLK_X + BLK_D + BLK_R);
        const float* W; int K, N; __half* T; int base;
        if (wb < 512)       { W = Wh1; K = 512;  N = HD; T = g_Wh1; base = 0;    }
        else if (wb < 1536) { W = Wc1; K = 1024; N = HD; T = g_Wc1; base = 512;  }
        else if (wb < 1792) { W = Wh2; K = 1024; N = LD; T = g_Wh2; base = 1536; }
        else                { W = Wc2; K = 1024; N = LD; T = g_Wc2; base = 1792; }
        int idx = wb - base;
        int nb  = N / 32;
        int n0  = (idx % nb) * 32;
        int k0  = (idx / nb) * 32;
        int x = tid & 31, y0 = tid >> 5;
        #pragma unroll
        for (int r = 0; r < 4; ++r) {
            int y = y0 + r * 8;
            s[y][x] = W[(long)(k0 + y) * N + n0 + x];
        }
        __syncthreads();
        #pragma unroll
        for (int r = 0; r < 4; ++r) {
            int y = y0 + r * 8;
            T[(long)(n0 + y) * K + k0 + x] = __float2half_rn(s[x][y]);
        }
    }
}

// ---------------------------------------------------------------------------
// mma.sync fp16 GEMM (single-term): C = act(A @ W^T + bias)
// CTA tile 128x128, BK=32, 256 thr / 8 warps (warp tile 64x32), batched blockIdx.z.
// 3-stage cp.async pipeline, one barrier per chunk. Stage: A 8K | B 8K. 48KB.
// PDL consumer: griddepcontrol.wait after preamble, before first global read.
// ---------------------------------------------------------------------------
#define BK      32
#define A_OFF   0u
#define B_OFF   8192u
#define STAGE   16384
#define NSTAGE  3

template<int ACT>
__global__ __launch_bounds__(256, 2)
void mma_gemm2(const __half* __restrict__ A0, const __half* __restrict__ B0,
               const float* __restrict__ bias0,
               __half* C0, float* Cf0, int K0,
               const __half* __restrict__ A1, const __half* __restrict__ B1,
               const float* __restrict__ bias1,
               __half* C1, float* Cf1, int K1,
               int lda, int ldc)
{
    extern __shared__ char smem[];
    const uint32_t sb = smem_u32(smem);
    const int tid  = threadIdx.x;
    const int wid  = tid >> 5;
    const int lane = tid & 31;
    const int wm   = wid >> 2;          // 0..1  (64-row slab)
    const int wn   = wid & 3;           // 0..3  (32-col slab)
    const int m0   = blockIdx.y * 128;
    const int n0   = blockIdx.x * 128;

    // per-z job select
    const int zz = blockIdx.z;
    const __half*  A   = zz ? A1   : A0;
    const __half*  B   = zz ? B1   : B0;
    const float*  bias = zz ? bias1 : bias0;
    __half*        C   = zz ? C1   : C0;
    float*         Cf  = zz ? Cf1  : Cf0;
    const int      K   = zz ? K1   : K0;

    // ---- cp.async copy mapping ----
    const int crow  = tid >> 1;
    const int chalf = tid & 1;
    const uint32_t csw = (uint32_t)((crow & 6) << 3);
    const uint32_t cd0 = (uint32_t)(crow * 64) + (((uint32_t)(chalf * 32) + 0u)  ^ csw);
    const uint32_t cd1 = (uint32_t)(crow * 64) + (((uint32_t)(chalf * 32) + 16u) ^ csw);

    const __half* gA = A + (size_t)(m0 + crow) * lda + chalf * 16;
    const __half* gB = B + (size_t)(n0 + crow) * K   + chalf * 16;

    // ---- ldmatrix fragment addressing ----
    const int g  = lane >> 3;
    const int l8 = lane & 7;
    const uint32_t fsw = (uint32_t)((l8 & 6) << 3);
    const uint32_t a_row = (uint32_t)(wm * 64 + (g & 1) * 8 + l8);
    const uint32_t b_row = (uint32_t)(wn * 32 + (g >> 1) * 8 + l8);
    uint32_t aCk[2], bCk[2];
    #pragma unroll
    for (int ka = 0; ka < 2; ++ka) {
        aCk[ka] = ((uint32_t)((g >> 1) * 16 + ka * 32)) ^ fsw;
        bCk[ka] = ((uint32_t)((g & 1)  * 16 + ka * 32)) ^ fsw;
    }
    const uint32_t aBase = a_row * 64u;
    const uint32_t bBase = b_row * 64u;

    float acc[4][4][4];
    #pragma unroll
    for (int i = 0; i < 4; ++i)
        #pragma unroll
        for (int j = 0; j < 4; ++j)
            #pragma unroll
            for (int r = 0; r < 4; ++r) acc[i][j][r] = 0.f;

    const int NC = K / BK;

    // PDL: producer kernel must be fully complete before we read its outputs.
    gdc_wait();

    // prologue: stage chunks 0,1
    #pragma unroll
    for (int p = 0; p < 2; ++p) {
        uint32_t st = sb + (uint32_t)p * STAGE;
        const int kc = p * BK;
        cpasync16(st + A_OFF + cd0, gA + kc);
        cpasync16(st + A_OFF + cd1, gA + kc + 8);
        cpasync16(st + B_OFF + cd0, gB + kc);
        cpasync16(st + B_OFF + cd1, gB + kc + 8);
        cp_commit();
    }

    int s_cons = 0;   // stage of chunk c
    int s_load = 2;   // stage of chunk c+2
    for (int c = 0; c < NC; ++c) {
        cp_wait1();                          // chunk c complete
        __syncthreads();                     // visibility + all warps done with chunk c-1

        if (c + 2 < NC) {
            const int kc = (c + 2) * BK;
            uint32_t st = sb + (uint32_t)s_load * STAGE;
            cpasync16(st + A_OFF + cd0, gA + kc);
            cpasync16(st + A_OFF + cd1, gA + kc + 8);
            cpasync16(st + B_OFF + cd0, gB + kc);
            cpasync16(st + B_OFF + cd1, gB + kc + 8);
        }
        cp_commit();

        // consume chunk c
        const uint32_t st = sb + (uint32_t)s_cons * STAGE;
        uint32_t bf[2][2][4];
        #pragma unroll
        for (int ka = 0; ka < 2; ++ka) {
            ldsm4(bf[ka][0], st + B_OFF + bBase +    0u + bCk[ka]);
            ldsm4(bf[ka][1], st + B_OFF + bBase + 1024u + bCk[ka]);
        }
        #pragma unroll
        for (int i = 0; i < 4; ++i) {
            uint32_t af[2][4];
            ldsm4(af[0], st + A_OFF + aBase + (uint32_t)(i * 1024) + aCk[0]);
            ldsm4(af[1], st + A_OFF + aBase + (uint32_t)(i * 1024) + aCk[1]);
            #pragma unroll
            for (int ka = 0; ka < 2; ++ka) {
                #pragma unroll
                for (int j = 0; j < 4; ++j) {
                    const uint32_t b0 = bf[ka][j >> 1][(j & 1) * 2];
                    const uint32_t b1 = bf[ka][j >> 1][(j & 1) * 2 + 1];
                    mma16816(acc[i][j], af[ka], b0, b1);
                }
            }
        }
        if (++s_cons == NSTAGE) s_cons = 0;
        if (++s_load == NSTAGE) s_load = 0;
    }

    // ---- epilogue (vectorized) ----
    const int quad = lane >> 2;
    const int tq   = lane & 3;
    #pragma unroll
    for (int i = 0; i < 4; ++i) {
        #pragma unroll
        for (int j = 0; j < 4; ++j) {
            const int m = m0 + wm * 64 + i * 16 + quad;
            const int cc = n0 + wn * 32 + j * 8 + tq * 2;
            const float bb0 = __ldg(bias + cc);
            const float bb1 = __ldg(bias + cc + 1);
            if (ACT) {
                float v00 = tanhf(acc[i][j][0] + bb0);
                float v01 = tanhf(acc[i][j][1] + bb1);
                float v10 = tanhf(acc[i][j][2] + bb0);
                float v11 = tanhf(acc[i][j][3] + bb1);
                __half2 p0; p0.x = __float2half_rn(v00); p0.y = __float2half_rn(v01);
                __half2 p1; p1.x = __float2half_rn(v10); p1.y = __float2half_rn(v11);
                *reinterpret_cast<__half2*>(C + (size_t)m * ldc + cc)       = p0;
                *reinterpret_cast<__half2*>(C + (size_t)(m + 8) * ldc + cc) = p1;
            } else {
                float2 v0; v0.x = acc[i][j][0] + bb0; v0.y = acc[i][j][1] + bb1;
                float2 v1; v1.x = acc[i][j][2] + bb0; v1.y = acc[i][j][3] + bb1;
                *reinterpret_cast<float2*>(Cf + (size_t)m * ldc + cc)       = v0;
                *reinterpret_cast<float2*>(Cf + (size_t)(m + 8) * ldc + cc) = v1;
            }
        }
    }
}

// ---------------------------------------------------------------------------
// K5: p2 copy + dkl. 4 rows/block, 64 thr/row, float4 loads. PDL consumer.
// ---------------------------------------------------------------------------
__global__ void final_kernel(const float* __restrict__ diffusion,
                             float* __restrict__ out)
{
    int tid = threadIdx.x;
    int row = blockIdx.x * 4 + (tid >> 6);
    int l   = tid & 63;                     // 0..63, 4 cols each
    int j0  = l * 4;

    gdc_wait();                              // wait for layer-2 completion

    float4 p1 = *reinterpret_cast<const float4*>(g_P1 + (long)row * LD + j0);
    float4 p2 = *reinterpret_cast<const float4*>(g_P2 + (long)row * LD + j0);

    float sq = 0.f;
    const float* p1p = &p1.x;
    const float* p2p = &p2.x;
    #pragma unroll
    for (int k = 0; k < 4; ++k) {
        float dif = diffusion[j0 + k];
        float sgn  = (dif > 0.f) ? 1.f : ((dif < 0.f) ? -1.f : 0.f);
        float sden = (fabsf(dif) > 1e-7f) ? dif : sgn * 1e-7f;
        float r = (p1p[k] - p2p[k]) / sden;
        sq += r * r;
    }

    // reduce over 64 lanes (2 warps per row-group)
    __shared__ float wsum[8];
    #pragma unroll
    for (int off = 16; off > 0; off >>= 1)
        sq += __shfl_down_sync(0xffffffffu, sq, off);
    if ((tid & 31) == 0) wsum[tid >> 5] = sq;
    __syncthreads();

    long dbase = (long)row * OUTC;
    float* orow = out + dbase + 256 + j0;
    orow[0] = p2.x; orow[1] = p2.y; orow[2] = p2.z; orow[3] = p2.w;

    if (l == 0) {
        int gbase = (tid >> 6) * 2;
        out[dbase + 512] = wsum[gbase] + wsum[gbase + 1];
    }
}

// ---------------------------------------------------------------------------
extern "C" void kernel_launch(void* const* d_in, const int* in_sizes, int n_in,
                              void* d_out, int out_size)
{
    const float* z    = (const float*)d_in[0];
    const float* ts   = (const float*)d_in[1];
    const float* t    = (const float*)d_in[2];
    const float* ctx  = (const float*)d_in[3];
    const float* im   = (const float*)d_in[4];
    const float* dif  = (const float*)d_in[5];
    const float* Wc1  = (const float*)d_in[6];
    const float* bc1  = (const float*)d_in[7];
    const float* Wc2  = (const float*)d_in[8];
    const float* bc2  = (const float*)d_in[9];
    const float* Wh1  = (const float*)d_in[10];
    const float* bh1  = (const float*)d_in[11];
    const float* Wh2  = (const float*)d_in[12];
    const float* bh2  = (const float*)d_in[13];
    float* out = (float*)d_out;

    __half *pX, *pH1, *pH2;
    __half *pWh1, *pWc1, *pWh2, *pWc2;
    float *pP1, *pP2;
    cudaGetSymbolAddress((void**)&pX,  g_X);
    cudaGetSymbolAddress((void**)&pH1, g_H1);
    cudaGetSymbolAddress((void**)&pH2, g_H2);
    cudaGetSymbolAddress((void**)&pP1, g_P1);
    cudaGetSymbolAddress((void**)&pP2, g_P2);
    cudaGetSymbolAddress((void**)&pWh1, g_Wh1);
    cudaGetSymbolAddress((void**)&pWc1, g_Wc1);
    cudaGetSymbolAddress((void**)&pWh2, g_Wh2);
    cudaGetSymbolAddress((void**)&pWc2, g_Wc2);

    const int smem_bytes = NSTAGE * STAGE;   // 48 KB
    cudaFuncSetAttribute(mma_gemm2<1>, cudaFuncAttributeMaxDynamicSharedMemorySize, smem_bytes);
    cudaFuncSetAttribute(mma_gemm2<0>, cudaFuncAttributeMaxDynamicSharedMemorySize, smem_bytes);

    // merged: X build + diffusion_out fill + drift head + weight transposes
    prep_kernel<<<BLK_X + BLK_D + BLK_R + BLK_W, 256>>>(
        z, ctx, ts, t, im, dif, Wh1, Wc1, Wh2, Wc2, out);

    cudaLaunchAttribute pdl[1];
    pdl[0].id = cudaLaunchAttributeProgrammaticStreamSerialization;
    pdl[0].val.programmaticStreamSerializationAllowed = 1;

    // Layer 1 (batched): z=0 H1 = tanh(pm@Wh1+bh1) K=512 ; z=1 H2 = tanh(X@Wc1+bc1) K=1024
    {
        cudaLaunchConfig_t cfg = {};
        cfg.gridDim  = dim3(HD / 128, NB / 128, 2);
        cfg.blockDim = dim3(256, 1, 1);
        cfg.dynamicSmemBytes = smem_bytes;
        cfg.stream = 0;
        cfg.attrs = pdl;
        cfg.numAttrs = 1;
        cudaLaunchKernelEx(&cfg, mma_gemm2<1>,
            (const __half*)pX, (const __half*)pWh1, bh1, pH1, (float*)nullptr, 512,
            (const __half*)pX, (const __half*)pWc1, bc1, pH2, (float*)nullptr, 1024,
            XK, HD);
    }

    // Layer 2 (batched): z=0 P1 -> g_P1 ; z=1 P2 -> g_P2
    {
        cudaLaunchConfig_t cfg = {};
        cfg.gridDim  = dim3(LD / 128, NB / 128, 2);
        cfg.blockDim = dim3(256, 1, 1);
        cfg.dynamicSmemBytes = smem_bytes;
        cfg.stream = 0;
        cfg.attrs = pdl;
        cfg.numAttrs = 1;
        cudaLaunchKernelEx(&cfg, mma_gemm2<0>,
            (const __half*)pH1, (const __half*)pWh2, bh2, (__half*)nullptr, pP1, 1024,
            (const __half*)pH2, (const __half*)pWc2, bc2, (__half*)nullptr, pP2, 1024,
            HD, LD);
    }

    // p2 copy + dkl
    {
        cudaLaunchConfig_t cfg = {};
        cfg.gridDim  = dim3(NB / 4, 1, 1);
        cfg.blockDim = dim3(256, 1, 1);
        cfg.dynamicSmemBytes = 0;
        cfg.stream = 0;
        cfg.attrs = pdl;
        cfg.numAttrs = 1;
        cudaLaunchKernelEx(&cfg, final_kernel, dif, out);
    }
}